// round 1
// baseline (speedup 1.0000x reference)
#include <cuda_runtime.h>

// LabelwiseAttention: B=4, S=4096, D=256, C=8921
//   scores[b,c,s] = sum_d x[b,s,d] * W[c,d]
//   attn = softmax_s(scores)
//   logits[b,c,d] = sum_s attn[b,c,s] * x[b,s,d]
// Output layout assumed: [logits (B*C*D) | attention (B*C*S)] fp32.
// Raw scores are written straight into the attention output region,
// softmaxed in place, then consumed by the second GEMM. No scratch memory.

#define BDIM 4
#define SDIM 4096
#define DDIM 256
#define CDIM 8921

// ---------------------------------------------------------------------------
// GEMM1 (NT): scores[c,s] = sum_k W[c,k] * x[s,k]    (both K-contiguous)
// 64x64 tile, BK=16, 256 threads, 4x4 per-thread micro-tile, float4 I/O.
// ---------------------------------------------------------------------------
__global__ void __launch_bounds__(256) gemm_scores_kernel(
    const float* __restrict__ W,
    const float* __restrict__ x,
    float* __restrict__ scores)
{
    __shared__ __align__(16) float As[16][64];  // [k][c]
    __shared__ __align__(16) float Bs[16][64];  // [k][s]

    const int b  = blockIdx.z;
    const float* xb   = x      + (size_t)b * SDIM * DDIM;
    float*       outb = scores + (size_t)b * CDIM * SDIM;

    const int c0 = blockIdx.y * 64;
    const int s0 = blockIdx.x * 64;

    const int tid = threadIdx.x;
    const int tr  = tid >> 4;          // 0..15 (c quad)
    const int tc  = tid & 15;          // 0..15 (s quad)
    const int lr  = tid >> 2;          // 0..63 load row
    const int lk  = (tid & 3) << 2;    // 0,4,8,12 load k offset

    float acc[4][4] = {};

    for (int k0 = 0; k0 < DDIM; k0 += 16) {
        float4 av = make_float4(0.f, 0.f, 0.f, 0.f);
        if (c0 + lr < CDIM)
            av = *(const float4*)(W + (size_t)(c0 + lr) * DDIM + k0 + lk);
        As[lk + 0][lr] = av.x; As[lk + 1][lr] = av.y;
        As[lk + 2][lr] = av.z; As[lk + 3][lr] = av.w;

        float4 bv = *(const float4*)(xb + (size_t)(s0 + lr) * DDIM + k0 + lk);
        Bs[lk + 0][lr] = bv.x; Bs[lk + 1][lr] = bv.y;
        Bs[lk + 2][lr] = bv.z; Bs[lk + 3][lr] = bv.w;

        __syncthreads();

#pragma unroll
        for (int k = 0; k < 16; k++) {
            float4 a4 = *(const float4*)&As[k][tr * 4];
            float4 b4 = *(const float4*)&Bs[k][tc * 4];
            float a[4] = {a4.x, a4.y, a4.z, a4.w};
            float bb[4] = {b4.x, b4.y, b4.z, b4.w};
#pragma unroll
            for (int i = 0; i < 4; i++)
#pragma unroll
                for (int j = 0; j < 4; j++)
                    acc[i][j] += a[i] * bb[j];
        }
        __syncthreads();
    }

#pragma unroll
    for (int i = 0; i < 4; i++) {
        const int c = c0 + tr * 4 + i;
        if (c < CDIM) {
#pragma unroll
            for (int j = 0; j < 4; j++)
                outb[(size_t)c * SDIM + s0 + tc * 4 + j] = acc[i][j];
        }
    }
}

// ---------------------------------------------------------------------------
// In-place row softmax over S=4096. One block per (b,c) row, 256 threads,
// 16 elements per thread held in registers (coalesced float4 accesses).
// ---------------------------------------------------------------------------
__global__ void __launch_bounds__(256) softmax_kernel(float* __restrict__ attn)
{
    float* p = attn + (size_t)blockIdx.x * SDIM;
    const int tid  = threadIdx.x;
    const int lane = tid & 31;
    const int wid  = tid >> 5;

    __shared__ float red[8];

    float4 v[4];
    float m = -3.0e38f;
#pragma unroll
    for (int i = 0; i < 4; i++) {
        v[i] = *(const float4*)(p + (size_t)(tid + i * 256) * 4);
        m = fmaxf(m, fmaxf(fmaxf(v[i].x, v[i].y), fmaxf(v[i].z, v[i].w)));
    }
#pragma unroll
    for (int o = 16; o > 0; o >>= 1)
        m = fmaxf(m, __shfl_xor_sync(0xffffffffu, m, o));
    if (lane == 0) red[wid] = m;
    __syncthreads();
    float bmax = red[0];
#pragma unroll
    for (int w = 1; w < 8; w++) bmax = fmaxf(bmax, red[w]);
    __syncthreads();   // everyone has read red[] before it is reused

    float s = 0.f;
#pragma unroll
    for (int i = 0; i < 4; i++) {
        v[i].x = expf(v[i].x - bmax);
        v[i].y = expf(v[i].y - bmax);
        v[i].z = expf(v[i].z - bmax);
        v[i].w = expf(v[i].w - bmax);
        s += (v[i].x + v[i].y) + (v[i].z + v[i].w);
    }
#pragma unroll
    for (int o = 16; o > 0; o >>= 1)
        s += __shfl_xor_sync(0xffffffffu, s, o);
    if (lane == 0) red[wid] = s;
    __syncthreads();
    float bsum = red[0];
#pragma unroll
    for (int w = 1; w < 8; w++) bsum += red[w];

    const float r = 1.0f / bsum;
#pragma unroll
    for (int i = 0; i < 4; i++) {
        v[i].x *= r; v[i].y *= r; v[i].z *= r; v[i].w *= r;
        *(float4*)(p + (size_t)(tid + i * 256) * 4) = v[i];
    }
}

// ---------------------------------------------------------------------------
// GEMM2 (NN): logits[c,d] = sum_s attn[c,s] * x[s,d]
// A is K-contiguous, B is N-contiguous. 64x64 tile, BK=16.
// ---------------------------------------------------------------------------
__global__ void __launch_bounds__(256) gemm_logits_kernel(
    const float* __restrict__ attn,
    const float* __restrict__ x,
    float* __restrict__ logits)
{
    __shared__ __align__(16) float As[16][64];  // [k][c]
    __shared__ __align__(16) float Bs[16][64];  // [k][d]

    const int b  = blockIdx.z;
    const float* ab = attn   + (size_t)b * CDIM * SDIM;
    const float* xb = x      + (size_t)b * SDIM * DDIM;
    float*       ob = logits + (size_t)b * CDIM * DDIM;

    const int c0 = blockIdx.y * 64;
    const int d0 = blockIdx.x * 64;

    const int tid = threadIdx.x;
    const int tr  = tid >> 4;
    const int tc  = tid & 15;
    const int lr  = tid >> 2;          // A: c row 0..63
    const int lk  = (tid & 3) << 2;    // A: k offset
    const int kb  = tid >> 4;          // B: s row 0..15
    const int nb  = (tid & 15) << 2;   // B: d offset

    float acc[4][4] = {};

    for (int k0 = 0; k0 < SDIM; k0 += 16) {
        float4 av = make_float4(0.f, 0.f, 0.f, 0.f);
        if (c0 + lr < CDIM)
            av = *(const float4*)(ab + (size_t)(c0 + lr) * SDIM + k0 + lk);
        As[lk + 0][lr] = av.x; As[lk + 1][lr] = av.y;
        As[lk + 2][lr] = av.z; As[lk + 3][lr] = av.w;

        *(float4*)&Bs[kb][nb] =
            *(const float4*)(xb + (size_t)(k0 + kb) * DDIM + d0 + nb);

        __syncthreads();

#pragma unroll
        for (int k = 0; k < 16; k++) {
            float4 a4 = *(const float4*)&As[k][tr * 4];
            float4 b4 = *(const float4*)&Bs[k][tc * 4];
            float a[4] = {a4.x, a4.y, a4.z, a4.w};
            float bb[4] = {b4.x, b4.y, b4.z, b4.w};
#pragma unroll
            for (int i = 0; i < 4; i++)
#pragma unroll
                for (int j = 0; j < 4; j++)
                    acc[i][j] += a[i] * bb[j];
        }
        __syncthreads();
    }

#pragma unroll
    for (int i = 0; i < 4; i++) {
        const int c = c0 + tr * 4 + i;
        if (c < CDIM) {
#pragma unroll
            for (int j = 0; j < 4; j++)
                ob[(size_t)c * DDIM + d0 + tc * 4 + j] = acc[i][j];
        }
    }
}

// ---------------------------------------------------------------------------
extern "C" void kernel_launch(void* const* d_in, const int* in_sizes, int n_in,
                              void* d_out, int out_size)
{
    const float* x = (const float*)d_in[0];   // [B, S, D]
    const float* W = (const float*)d_in[1];   // [C, D]

    float* logits = (float*)d_out;                                   // [B, C, D]
    float* attn   = (float*)d_out + (size_t)BDIM * CDIM * DDIM;      // [B, C, S]

    // 1) raw scores -> attention region
    dim3 g1(SDIM / 64, (CDIM + 63) / 64, BDIM);
    gemm_scores_kernel<<<g1, 256>>>(W, x, attn);

    // 2) softmax rows in place
    softmax_kernel<<<BDIM * CDIM, 256>>>(attn);

    // 3) logits = attn @ x
    dim3 g2(DDIM / 64, (CDIM + 63) / 64, BDIM);
    gemm_logits_kernel<<<g2, 256>>>(attn, x, logits);
}

// round 4
// speedup vs baseline: 2.6559x; 2.6559x over previous
#include <cuda_runtime.h>
#include <cuda_bf16.h>
#include <cstdint>

// LabelwiseAttention: B=4, S=4096, D=256, C=8921
// scores = x @ W^T -> softmax over S -> logits = attn @ x
// Output: [logits (B*C*D) | attention (B*C*S)] fp32.
// GEMMs: mma.sync.m16n8k16 bf16 (sm_80-class path; tcgen05 unavailable on
// this toolchain's compute_103 target), bf16x3 split precision, fp32 acc.

#define BDIM 4
#define SDIM 4096
#define DDIM 256
#define CDIM 8921

#define BM 128
#define BN 128
#define BK 32
// smem: per stage 4 operand tiles (Ahi,Alo,Bhi,Blo), each 128 rows x 80B
#define ROWPITCH 80
#define TILEBYTES (128 * ROWPITCH)          // 10240
#define STAGEBYTES (4 * TILEBYTES)          // 40960
#define SM_TOTAL (2 * STAGEBYTES)           // 81920

// ---------------- scratch (device globals; allocation-free rule) -----------
__device__ __nv_bfloat16 g_xhi[(size_t)BDIM * SDIM * DDIM];
__device__ __nv_bfloat16 g_xlo[(size_t)BDIM * SDIM * DDIM];
__device__ __nv_bfloat16 g_xThi[(size_t)BDIM * DDIM * SDIM];
__device__ __nv_bfloat16 g_xTlo[(size_t)BDIM * DDIM * SDIM];
__device__ __nv_bfloat16 g_Whi[(size_t)CDIM * DDIM];
__device__ __nv_bfloat16 g_Wlo[(size_t)CDIM * DDIM];
__device__ __nv_bfloat16 g_ahi[(size_t)BDIM * CDIM * SDIM];
__device__ __nv_bfloat16 g_alo[(size_t)BDIM * CDIM * SDIM];

// ---------------- helpers ---------------------------------------------------
__device__ __forceinline__ uint32_t smem_u32(const void* p) {
    uint32_t a;
    asm("{ .reg .u64 t; cvta.to.shared.u64 t, %1; cvt.u32.u64 %0, t; }"
        : "=r"(a) : "l"(p));
    return a;
}

__device__ __forceinline__ void cp16(uint32_t dst, const void* src, int sz) {
    asm volatile("cp.async.cg.shared.global [%0], [%1], 16, %2;"
                 :: "r"(dst), "l"(src), "r"(sz) : "memory");
}
#define CP_COMMIT() asm volatile("cp.async.commit_group;" ::: "memory")
#define CP_WAIT1()  asm volatile("cp.async.wait_group 1;" ::: "memory")

__device__ __forceinline__ void ldm4(uint32_t* r, uint32_t addr) {
    asm volatile("ldmatrix.sync.aligned.m8n8.x4.shared.b16 {%0,%1,%2,%3}, [%4];"
                 : "=r"(r[0]), "=r"(r[1]), "=r"(r[2]), "=r"(r[3]) : "r"(addr));
}

__device__ __forceinline__ void mma16816(float* d, const uint32_t* a,
                                         uint32_t b0, uint32_t b1) {
    asm volatile(
        "mma.sync.aligned.m16n8k16.row.col.f32.bf16.bf16.f32 "
        "{%0,%1,%2,%3}, {%4,%5,%6,%7}, {%8,%9}, {%0,%1,%2,%3};"
        : "+f"(d[0]), "+f"(d[1]), "+f"(d[2]), "+f"(d[3])
        : "r"(a[0]), "r"(a[1]), "r"(a[2]), "r"(a[3]), "r"(b0), "r"(b1));
}

// ---------------- split kernels ---------------------------------------------
__global__ void split_W_kernel(const float* __restrict__ W) {
    int i = blockIdx.x * 256 + threadIdx.x;
    if (i < CDIM * DDIM) {
        float v = W[i];
        __nv_bfloat16 h = __float2bfloat16(v);
        g_Whi[i] = h;
        g_Wlo[i] = __float2bfloat16(v - __bfloat162float(h));
    }
}

__global__ void split_x_kernel(const float* __restrict__ x) {
    __shared__ __nv_bfloat16 th[32][33], tl[32][33];
    const int b = blockIdx.z;
    const int s0 = blockIdx.x * 32, d0 = blockIdx.y * 32;
    const int tx = threadIdx.x, ty = threadIdx.y;  // 32x8
    const float* xb = x + (size_t)b * SDIM * DDIM;
#pragma unroll
    for (int i = 0; i < 32; i += 8) {
        int s = s0 + ty + i;
        float v = xb[(size_t)s * DDIM + d0 + tx];
        __nv_bfloat16 h = __float2bfloat16(v);
        __nv_bfloat16 l = __float2bfloat16(v - __bfloat162float(h));
        size_t o = (size_t)b * SDIM * DDIM + (size_t)s * DDIM + d0 + tx;
        g_xhi[o] = h;
        g_xlo[o] = l;
        th[ty + i][tx] = h;
        tl[ty + i][tx] = l;
    }
    __syncthreads();
#pragma unroll
    for (int i = 0; i < 32; i += 8) {
        int d = d0 + ty + i;
        size_t o = (size_t)b * DDIM * SDIM + (size_t)d * SDIM + s0 + tx;
        g_xThi[o] = th[tx][ty + i];
        g_xTlo[o] = tl[tx][ty + i];
    }
}

// ---------------- softmax (in place) + bf16 split emit ----------------------
__global__ void __launch_bounds__(256) softmax_kernel(float* __restrict__ attn) {
    const size_t base = (size_t)blockIdx.x * SDIM;
    float* p = attn + base;
    const int tid = threadIdx.x;
    const int lane = tid & 31;
    const int wid = tid >> 5;

    __shared__ float red[8];

    float4 v[4];
    float m = -3.0e38f;
#pragma unroll
    for (int i = 0; i < 4; i++) {
        v[i] = *(const float4*)(p + (size_t)(tid + i * 256) * 4);
        m = fmaxf(m, fmaxf(fmaxf(v[i].x, v[i].y), fmaxf(v[i].z, v[i].w)));
    }
#pragma unroll
    for (int o = 16; o > 0; o >>= 1) m = fmaxf(m, __shfl_xor_sync(0xffffffffu, m, o));
    if (lane == 0) red[wid] = m;
    __syncthreads();
    float bmax = red[0];
#pragma unroll
    for (int w = 1; w < 8; w++) bmax = fmaxf(bmax, red[w]);
    __syncthreads();

    float s = 0.f;
#pragma unroll
    for (int i = 0; i < 4; i++) {
        v[i].x = expf(v[i].x - bmax);
        v[i].y = expf(v[i].y - bmax);
        v[i].z = expf(v[i].z - bmax);
        v[i].w = expf(v[i].w - bmax);
        s += (v[i].x + v[i].y) + (v[i].z + v[i].w);
    }
#pragma unroll
    for (int o = 16; o > 0; o >>= 1) s += __shfl_xor_sync(0xffffffffu, s, o);
    if (lane == 0) red[wid] = s;
    __syncthreads();
    float bsum = red[0];
#pragma unroll
    for (int w = 1; w < 8; w++) bsum += red[w];

    const float r = 1.0f / bsum;
#pragma unroll
    for (int i = 0; i < 4; i++) {
        v[i].x *= r; v[i].y *= r; v[i].z *= r; v[i].w *= r;
        const size_t off = (size_t)(tid + i * 256) * 4;
        *(float4*)(p + off) = v[i];
        float vs[4] = {v[i].x, v[i].y, v[i].z, v[i].w};
        __nv_bfloat16 h[4], l[4];
#pragma unroll
        for (int j = 0; j < 4; j++) {
            h[j] = __float2bfloat16(vs[j]);
            l[j] = __float2bfloat16(vs[j] - __bfloat162float(h[j]));
        }
        *(uint2*)(g_ahi + base + off) = *(const uint2*)h;
        *(uint2*)(g_alo + base + off) = *(const uint2*)l;
    }
}

// ---------------- bf16x3 split GEMM on mma.sync -----------------------------
// Out[m,n] (+bounds m<Mv) = sum_k (Ahi+Alo)[m,k]*(Bhi+Blo)[n,k]  (drop lo*lo)
// A: [*,K] K-major rows m0..; B: [*,K] K-major rows n0..; K % 32 == 0.
__global__ void __launch_bounds__(256, 1) mma_gemm(
    const __nv_bfloat16* __restrict__ Ahi, const __nv_bfloat16* __restrict__ Alo,
    size_t sA, int Mv,
    const __nv_bfloat16* __restrict__ Bhi, const __nv_bfloat16* __restrict__ Blo,
    size_t sB,
    float* __restrict__ Out, size_t sO, int ldo, int K)
{
    extern __shared__ char sm[];
    const uint32_t sbase = smem_u32(sm);

    const int tid = threadIdx.x;
    const int lane = tid & 31;
    const int wid = tid >> 5;
    const int wm = wid & 1;        // 0..1 -> 64-row slab
    const int wn = wid >> 1;       // 0..3 -> 32-col slab
    const int b = blockIdx.z;
    const int m0 = blockIdx.y * BM;
    const int n0 = blockIdx.x * BN;

    const __nv_bfloat16* Ah = Ahi + sA * b;
    const __nv_bfloat16* Al = Alo + sA * b;
    const __nv_bfloat16* Bh = Bhi + sB * b;
    const __nv_bfloat16* Bl = Blo + sB * b;

    float acc[4][4][4];
#pragma unroll
    for (int i = 0; i < 4; i++)
#pragma unroll
        for (int j = 0; j < 4; j++)
#pragma unroll
            for (int q = 0; q < 4; q++) acc[i][j][q] = 0.f;

    const int NC = K / BK;

    // ---- stage loader: 4 operands x 128 rows x 4 chunks(16B) ----
    auto issue = [&](int kc) {
        const uint32_t st = sbase + (uint32_t)(kc & 1) * STAGEBYTES;
        const int k0 = kc * BK;
#pragma unroll
        for (int it = 0; it < 2; it++) {
            const int idx = tid + it * 256;
            const int row = idx >> 2, ch = idx & 3;
            const uint32_t soff = (uint32_t)(row * ROWPITCH + ch * 16);
            const int ra = m0 + row;
            const int sz = (ra < Mv) ? 16 : 0;
            const int rac = (ra < Mv) ? ra : (Mv - 1);
            const size_t ga = (size_t)rac * K + k0 + ch * 8;
            cp16(st + soff, Ah + ga, sz);
            cp16(st + TILEBYTES + soff, Al + ga, sz);
            const size_t gb = (size_t)(n0 + row) * K + k0 + ch * 8;
            cp16(st + 2 * TILEBYTES + soff, Bh + gb, 16);
            cp16(st + 3 * TILEBYTES + soff, Bl + gb, 16);
        }
    };

    issue(0); CP_COMMIT();
    if (NC > 1) issue(1);
    CP_COMMIT();

    // frag address pieces (within a 128x32 tile, 80B pitch)
    const uint32_t aoff = (uint32_t)((lane & 15) * ROWPITCH + (lane >> 4) * 16);
    const uint32_t boff = (uint32_t)(((lane & 7) + (lane >> 4) * 8) * ROWPITCH +
                                     ((lane >> 3) & 1) * 16);

    for (int kc = 0; kc < NC; kc++) {
        CP_WAIT1();
        __syncthreads();
        const uint32_t st = sbase + (uint32_t)(kc & 1) * STAGEBYTES;

#pragma unroll
        for (int ks = 0; ks < 2; ks++) {
            const uint32_t kb = ks * 32;
            uint32_t ahf[4][4], alf[4][4], bhf[2][4], blf[2][4];
#pragma unroll
            for (int mi = 0; mi < 4; mi++) {
                const uint32_t base =
                    st + (uint32_t)((wm * 64 + mi * 16) * ROWPITCH) + kb + aoff;
                ldm4(ahf[mi], base);
                ldm4(alf[mi], base + TILEBYTES);
            }
#pragma unroll
            for (int pi = 0; pi < 2; pi++) {
                const uint32_t base = st + 2 * TILEBYTES +
                    (uint32_t)((wn * 32 + pi * 16) * ROWPITCH) + kb + boff;
                ldm4(bhf[pi], base);
                ldm4(blf[pi], base + TILEBYTES);
            }
#pragma unroll
            for (int mi = 0; mi < 4; mi++) {
#pragma unroll
                for (int ni = 0; ni < 4; ni++) {
                    const int p = ni >> 1, w2 = (ni & 1) * 2;
                    mma16816(acc[mi][ni], ahf[mi], bhf[p][w2], bhf[p][w2 + 1]);
                    mma16816(acc[mi][ni], ahf[mi], blf[p][w2], blf[p][w2 + 1]);
                    mma16816(acc[mi][ni], alf[mi], bhf[p][w2], bhf[p][w2 + 1]);
                }
            }
        }
        __syncthreads();
        if (kc + 2 < NC) issue(kc + 2);
        CP_COMMIT();
    }

    // ---- epilogue ----
    const int g = lane >> 2, cq = lane & 3;
    float* ob = Out + sO * b;
#pragma unroll
    for (int mi = 0; mi < 4; mi++) {
        const int r0 = m0 + wm * 64 + mi * 16 + g;
        const int r1 = r0 + 8;
#pragma unroll
        for (int ni = 0; ni < 4; ni++) {
            const int col = n0 + wn * 32 + ni * 8 + cq * 2;
            if (r0 < Mv)
                *(float2*)(ob + (size_t)r0 * ldo + col) =
                    make_float2(acc[mi][ni][0], acc[mi][ni][1]);
            if (r1 < Mv)
                *(float2*)(ob + (size_t)r1 * ldo + col) =
                    make_float2(acc[mi][ni][2], acc[mi][ni][3]);
        }
    }
}

// ---------------------------------------------------------------------------
extern "C" void kernel_launch(void* const* d_in, const int* in_sizes, int n_in,
                              void* d_out, int out_size)
{
    const float* x = (const float*)d_in[0];  // [B, S, D]
    const float* W = (const float*)d_in[1];  // [C, D]

    float* logits = (float*)d_out;                               // [B, C, D]
    float* attn   = (float*)d_out + (size_t)BDIM * CDIM * DDIM;  // [B, C, S]

    cudaFuncSetAttribute(mma_gemm,
                         cudaFuncAttributeMaxDynamicSharedMemorySize, SM_TOTAL);

    void *p_xhi, *p_xlo, *p_xThi, *p_xTlo, *p_Whi, *p_Wlo, *p_ahi, *p_alo;
    cudaGetSymbolAddress(&p_xhi, g_xhi);
    cudaGetSymbolAddress(&p_xlo, g_xlo);
    cudaGetSymbolAddress(&p_xThi, g_xThi);
    cudaGetSymbolAddress(&p_xTlo, g_xTlo);
    cudaGetSymbolAddress(&p_Whi, g_Whi);
    cudaGetSymbolAddress(&p_Wlo, g_Wlo);
    cudaGetSymbolAddress(&p_ahi, g_ahi);
    cudaGetSymbolAddress(&p_alo, g_alo);

    // 1) bf16 splits of W and x (+ transposed x)
    split_W_kernel<<<(CDIM * DDIM + 255) / 256, 256>>>(W);
    split_x_kernel<<<dim3(SDIM / 32, DDIM / 32, BDIM), dim3(32, 8)>>>(x);

    // 2) scores = x @ W^T -> attention region (raw fp32 scores)
    //    A = W [C, D] (no batch stride), B = x [S, D], K = 256
    mma_gemm<<<dim3(SDIM / BN, (CDIM + BM - 1) / BM, BDIM), 256, SM_TOTAL>>>(
        (const __nv_bfloat16*)p_Whi, (const __nv_bfloat16*)p_Wlo, (size_t)0, CDIM,
        (const __nv_bfloat16*)p_xhi, (const __nv_bfloat16*)p_xlo,
        (size_t)SDIM * DDIM,
        attn, (size_t)CDIM * SDIM, SDIM, DDIM);

    // 3) softmax rows in place + emit bf16 hi/lo splits of attention
    softmax_kernel<<<BDIM * CDIM, 256>>>(attn);

    // 4) logits = attn @ x ; A = attn-split [C, S], B = xT [D, S], K = 4096
    mma_gemm<<<dim3(DDIM / BN, (CDIM + BM - 1) / BM, BDIM), 256, SM_TOTAL>>>(
        (const __nv_bfloat16*)p_ahi, (const __nv_bfloat16*)p_alo,
        (size_t)CDIM * SDIM, CDIM,
        (const __nv_bfloat16*)p_xThi, (const __nv_bfloat16*)p_xTlo,
        (size_t)DDIM * SDIM,
        logits, (size_t)CDIM * DDIM, DDIM, SDIM);
}